// round 2
// baseline (speedup 1.0000x reference)
#include <cuda_runtime.h>
#include <math.h>

// ---------------------------------------------------------------------------
// TaskGraphGAT fused kernel (fp32 SIMT baseline, round 1)
//
// Shapes: B=16384 (from in_sizes), N=8 tasks, HID=128, H=4 heads, L=2 layers.
// One CTA processes TB=16 batch elements = 128 rows of [*,128] features,
// runs BOTH GAT layers entirely in shared memory, writes final h.
// ---------------------------------------------------------------------------

#define HP 136          // SMEM row pitch in floats (mult of 8 for float4 align)
#define TB 16           // batch elements per CTA

__device__ float g_htask[8 * 128];  // task_embeddings @ W_in^T + b_in
__device__ float g_ew[64];          // masked edge weights

// --- tiny setup kernel: edge weights + task projection -----------------------
__global__ void setup_kernel(const float* __restrict__ te,
                             const float* __restrict__ W_in,
                             const float* __restrict__ b_in,
                             const float* __restrict__ om_i,
                             const float* __restrict__ om_c,
                             const int* __restrict__ adj,
                             const int* __restrict__ et,
                             float* __restrict__ out_tail)
{
    int t = threadIdx.x;
    if (t < 64) {
        float w = 0.0f;
        if (adj[t] != 0) {
            int e = et[t];
            w = (e == 1) ? om_i[0] : ((e == 2) ? om_c[0] : 1.0f);
        }
        g_ew[t] = w;
        out_tail[t] = w;   // second output of the reference tuple
    }
    // h_task[n][o] = sum_d te[n][d] * W_in[o][d] + b_in[o]   (8 x 128, K=64)
    for (int idx = t; idx < 8 * 128; idx += blockDim.x) {
        int n = idx >> 7, o = idx & 127;
        const float* tr = te + n * 64;
        const float* wr = W_in + o * 64;
        float s = b_in[o];
#pragma unroll 8
        for (int d = 0; d < 64; d++) s += tr[d] * wr[d];
        g_htask[idx] = s;
    }
}

// --- main fused kernel -------------------------------------------------------
__global__ __launch_bounds__(256, 1)
void gat_kernel(const float* __restrict__ se,        // [B,128]
                const float* __restrict__ W_heads,   // [2,4,128,128]
                const float* __restrict__ a_heads,   // [2,4,256]
                const float* __restrict__ out_W,     // [2,128,512]
                const float* __restrict__ out_b,     // [2,128]
                const float* __restrict__ ln_scale,  // [2,128]
                const float* __restrict__ ln_bias,   // [2,128]
                const int*   __restrict__ adj,       // [8,8]
                float* __restrict__ out)             // [B,8,128] (+64 tail)
{
    extern __shared__ float sm[];
    float* hT    = sm;                 // [f][r]  feature-major h, 128 x HP
    float* bufA  = sm + 128 * HP;      // W^T chunk, then Whh [r][g], then hp [r][g]
    float* bufB  = bufA + 128 * HP;    // outW^T chunk [g][c], LN scratch
    float* att_s = bufB + 128 * HP;    // [16][8][8]
    float* ei_s  = att_s + 1024;       // [128]
    float* ej_s  = ei_s + 128;         // [128]
    float* ew_s  = ej_s + 128;         // [64]
    int*   adj_s = (int*)(ew_s + 64);  // [64]

    const int tid = threadIdx.x;
    const int tx  = tid & 15;
    const int ty  = tid >> 4;
    const int r0  = ty * 8;            // this thread's 8 rows (one batch elem: b=ty)
    const int c0  = tx * 8;            // this thread's 8 cols
    const long b0 = (long)blockIdx.x * TB;

    if (tid < 64) { adj_s[tid] = adj[tid]; ew_s[tid] = g_ew[tid]; }

    // h[r][f] = shared_embedding[b][f] + h_task[n][f], stored feature-major
    for (int idx = tid; idx < 128 * 128; idx += 256) {
        int r = idx >> 7, f = idx & 127;
        hT[f * HP + r] = se[(b0 + (r >> 3)) * 128 + f] + g_htask[((r & 7) << 7) + f];
    }
    __syncthreads();

    for (int l = 0; l < 2; l++) {
        float gacc[8][8];   // gout accumulator, persists across heads
#pragma unroll
        for (int i = 0; i < 8; i++)
#pragma unroll
            for (int j = 0; j < 8; j++) gacc[i][j] = 0.0f;

        for (int hh = 0; hh < 4; hh++) {
            // stage W_heads[l][hh] transposed: bufA[f][g]
            const float* Wg = W_heads + ((long)(l * 4 + hh) << 14);
            for (int idx = tid; idx < 16384; idx += 256) {
                int g = idx >> 7, f = idx & 127;
                bufA[f * HP + g] = Wg[(g << 7) + f];
            }
            // stage out_W chunk transposed: bufB[g][c] = out_W[l][c][hh*128+g]
            const float* OWg = out_W + ((long)l << 16) + (hh << 7);
            for (int idx = tid; idx < 16384; idx += 256) {
                int c = idx >> 7, g = idx & 127;
                bufB[g * HP + c] = OWg[(c << 9) + g];
            }
            __syncthreads();

            // ---- GEMM1: Whh[r][g] = sum_f h[r][f] * W[g][f] ----
            float acc[8][8];
#pragma unroll
            for (int i = 0; i < 8; i++)
#pragma unroll
                for (int j = 0; j < 8; j++) acc[i][j] = 0.0f;

#pragma unroll 4
            for (int f = 0; f < 128; f++) {
                float av[8], bv[8];
                *(float4*)&av[0] = *(const float4*)&hT[f * HP + r0];
                *(float4*)&av[4] = *(const float4*)&hT[f * HP + r0 + 4];
                *(float4*)&bv[0] = *(const float4*)&bufA[f * HP + c0];
                *(float4*)&bv[4] = *(const float4*)&bufA[f * HP + c0 + 4];
#pragma unroll
                for (int i = 0; i < 8; i++)
#pragma unroll
                    for (int j = 0; j < 8; j++) acc[i][j] += av[i] * bv[j];
            }
            __syncthreads();   // all reads of W chunk done

            // store Whh row-major [r][g] (conflict-free float4 stores)
#pragma unroll
            for (int i = 0; i < 8; i++) {
                *(float4*)&bufA[(r0 + i) * HP + c0] =
                    make_float4(acc[i][0], acc[i][1], acc[i][2], acc[i][3]);
                *(float4*)&bufA[(r0 + i) * HP + c0 + 4] =
                    make_float4(acc[i][4], acc[i][5], acc[i][6], acc[i][7]);
            }
            __syncthreads();

            // ---- attention scores ----
            const float* av_ = a_heads + (l * 4 + hh) * 256;
            if (tid < 128) {
                float sei = 0.0f, sej = 0.0f;
#pragma unroll 4
                for (int g = 0; g < 128; g++) {
                    float v = bufA[tid * HP + g];
                    sei += v * av_[g];
                    sej += v * av_[128 + g];
                }
                ei_s[tid] = sei;
                ej_s[tid] = sej;
            }
            __syncthreads();

            if (tid < 128) {
                int bb = tid >> 3, n = tid & 7;
                float ein = ei_s[tid];
                float lg[8];
                float mx = -1e30f;
#pragma unroll
                for (int m = 0; m < 8; m++) {
                    float v = 0.0f;   // masked entries: logit 0 (faithful to ref)
                    if (adj_s[n * 8 + m]) {
                        float x = ein + ej_s[bb * 8 + m];
                        v = (x > 0.0f ? x : 0.2f * x) * ew_s[n * 8 + m];
                    }
                    lg[m] = v;
                    mx = fmaxf(mx, v);
                }
                float s = 0.0f;
#pragma unroll
                for (int m = 0; m < 8; m++) { lg[m] = __expf(lg[m] - mx); s += lg[m]; }
                float inv = 1.0f / s;
#pragma unroll
                for (int m = 0; m < 8; m++) att_s[tid * 8 + m] = lg[m] * inv;
            }
            __syncthreads();

            // ---- hp = elu(att @ Whh) ; rows r0..r0+7 all belong to b=ty ----
            float hp[8][8];
#pragma unroll
            for (int i = 0; i < 8; i++)
#pragma unroll
                for (int j = 0; j < 8; j++) hp[i][j] = 0.0f;

#pragma unroll
            for (int m = 0; m < 8; m++) {
                float bv[8];
                *(float4*)&bv[0] = *(const float4*)&bufA[(r0 + m) * HP + c0];
                *(float4*)&bv[4] = *(const float4*)&bufA[(r0 + m) * HP + c0 + 4];
#pragma unroll
                for (int i = 0; i < 8; i++) {
                    float a = att_s[(r0 + i) * 8 + m];
#pragma unroll
                    for (int j = 0; j < 8; j++) hp[i][j] += a * bv[j];
                }
            }
#pragma unroll
            for (int i = 0; i < 8; i++)
#pragma unroll
                for (int j = 0; j < 8; j++) {
                    float x = hp[i][j];
                    hp[i][j] = x > 0.0f ? x : (__expf(x) - 1.0f);
                }
            __syncthreads();   // Whh reads done before overwrite

            // store hp row-major [r][g]
#pragma unroll
            for (int i = 0; i < 8; i++) {
                *(float4*)&bufA[(r0 + i) * HP + c0] =
                    make_float4(hp[i][0], hp[i][1], hp[i][2], hp[i][3]);
                *(float4*)&bufA[(r0 + i) * HP + c0 + 4] =
                    make_float4(hp[i][4], hp[i][5], hp[i][6], hp[i][7]);
            }
            __syncthreads();

            // ---- GEMM2: gacc[r][c] += sum_g hp[r][g] * outW[c][hh*128+g] ----
#pragma unroll 2
            for (int g = 0; g < 128; g++) {
                float av2[8], bv2[8];
#pragma unroll
                for (int i = 0; i < 8; i++) av2[i] = bufA[(r0 + i) * HP + g];
                *(float4*)&bv2[0] = *(const float4*)&bufB[g * HP + c0];
                *(float4*)&bv2[4] = *(const float4*)&bufB[g * HP + c0 + 4];
#pragma unroll
                for (int i = 0; i < 8; i++)
#pragma unroll
                    for (int j = 0; j < 8; j++) gacc[i][j] += av2[i] * bv2[j];
            }
            __syncthreads();   // done with both staged chunks
        } // heads

        // gout -> bufA row-major for LN
#pragma unroll
        for (int i = 0; i < 8; i++) {
            *(float4*)&bufA[(r0 + i) * HP + c0] =
                make_float4(gacc[i][0], gacc[i][1], gacc[i][2], gacc[i][3]);
            *(float4*)&bufA[(r0 + i) * HP + c0 + 4] =
                make_float4(gacc[i][4], gacc[i][5], gacc[i][6], gacc[i][7]);
        }
        __syncthreads();

        // ---- residual + LayerNorm, one thread per row ----
        if (tid < 128) {
            int r = tid;
            const float* ob = out_b + l * 128;
            float sum = 0.0f, sq = 0.0f;
            for (int f = 0; f < 128; f++) {
                float v = hT[f * HP + r] + bufA[r * HP + f] + ob[f];
                bufB[r * HP + f] = v;
                sum += v; sq += v * v;
            }
            float mu   = sum * 0.0078125f;               // /128
            float var  = sq * 0.0078125f - mu * mu;
            float rstd = rsqrtf(var + 1e-5f);
            const float* sc = ln_scale + l * 128;
            const float* bi = ln_bias  + l * 128;
            for (int f = 0; f < 128; f++) {
                hT[f * HP + r] = (bufB[r * HP + f] - mu) * rstd * sc[f] + bi[f];
            }
        }
        __syncthreads();
    } // layers

    // write final h, coalesced over features
    for (int idx = tid; idx < 128 * 128; idx += 256) {
        int r = idx >> 7, f = idx & 127;
        out[(b0 * 8 + r) * 128 + f] = hT[f * HP + r];
    }
}

// ---------------------------------------------------------------------------
extern "C" void kernel_launch(void* const* d_in, const int* in_sizes, int n_in,
                              void* d_out, int out_size)
{
    const float* se       = (const float*)d_in[0];
    const float* te       = (const float*)d_in[1];
    const float* W_in     = (const float*)d_in[2];
    const float* b_in     = (const float*)d_in[3];
    const float* W_heads  = (const float*)d_in[4];
    const float* a_heads  = (const float*)d_in[5];
    const float* out_W    = (const float*)d_in[6];
    const float* out_b    = (const float*)d_in[7];
    const float* ln_s     = (const float*)d_in[8];
    const float* ln_b     = (const float*)d_in[9];
    const float* om_i     = (const float*)d_in[10];
    const float* om_c     = (const float*)d_in[11];
    const int*   adj      = (const int*)d_in[12];
    const int*   et       = (const int*)d_in[13];
    float* out = (float*)d_out;

    int B = in_sizes[0] / 128;
    size_t tail = (size_t)B * 8 * 128;

    int smem_bytes = (3 * 128 * HP + 1024 + 128 + 128 + 64 + 64) * sizeof(float);
    cudaFuncSetAttribute(gat_kernel,
                         cudaFuncAttributeMaxDynamicSharedMemorySize, smem_bytes);

    setup_kernel<<<1, 512>>>(te, W_in, b_in, om_i, om_c, adj, et, out + tail);
    gat_kernel<<<B / TB, 256, smem_bytes>>>(se, W_heads, a_heads, out_W, out_b,
                                            ln_s, ln_b, adj, out);
}

// round 4
// speedup vs baseline: 2.7682x; 2.7682x over previous
#include <cuda_runtime.h>
#include <cuda_bf16.h>
#include <cstdint>
#include <math.h>

// ===========================================================================
// TaskGraphGAT — round 3: mma.sync (HMMA bf16, double-bf16 3-product)
// 1 CTA = 16 batch elems = 128 rows; both layers fully in SMEM.
// No tcgen05 (ptxas target is plain compute_103): ldmatrix + mma.sync only.
// ===========================================================================

#define PB   272        // bf16 tile pitch in BYTES (136 bf16) -> LDSM conflict-free
#define SCRP 132        // fp32 scratch pitch in floats

// ---------------- SMEM map (bytes) ----------------
#define SM_HHI   0          // h hi   (128 x 136 bf16 = 34816 B)
#define SM_HLO   34816
#define SM_PHI   69632      // W hi -> hp hi   (GEMM1 B / GEMM2 A)
#define SM_PLO   104448
#define SM_S     139264     // Whh fp32 scratch  OR  outW hi+lo tiles (69632 B)
#define SM_SLO   174080     // outW lo half of S region
#define SM_SMALL 208896
#define SMEM_BYTES 217600

// ---------------- device globals ----------------
__device__ float g_htask[8 * 128];
__device__ float g_ew[64];
__device__ __align__(16) __nv_bfloat16 g_Whi[8 * 16384];
__device__ __align__(16) __nv_bfloat16 g_Wlo[8 * 16384];
__device__ __align__(16) __nv_bfloat16 g_OWhi[8 * 16384];
__device__ __align__(16) __nv_bfloat16 g_OWlo[8 * 16384];

// ---------------- helpers ----------------
__device__ __forceinline__ uint32_t smem_u32(const void* p) {
    uint32_t a;
    asm("{ .reg .u64 t; cvta.to.shared.u64 t, %1; cvt.u32.u64 %0, t; }" : "=r"(a) : "l"(p));
    return a;
}
__device__ __forceinline__ void ldsm4(uint32_t* r, uint32_t a) {
    asm volatile("ldmatrix.sync.aligned.m8n8.x4.shared.b16 {%0,%1,%2,%3}, [%4];"
                 : "=r"(r[0]), "=r"(r[1]), "=r"(r[2]), "=r"(r[3]) : "r"(a));
}
__device__ __forceinline__ void mma16816(float* c, const uint32_t* a, const uint32_t* b) {
    asm volatile(
        "mma.sync.aligned.m16n8k16.row.col.f32.bf16.bf16.f32 "
        "{%0,%1,%2,%3}, {%4,%5,%6,%7}, {%8,%9}, {%0,%1,%2,%3};"
        : "+f"(c[0]), "+f"(c[1]), "+f"(c[2]), "+f"(c[3])
        : "r"(a[0]), "r"(a[1]), "r"(a[2]), "r"(a[3]), "r"(b[0]), "r"(b[1]));
}
__device__ __forceinline__ uint32_t pack2(float x0, float x1) {
    __nv_bfloat162 v = __floats2bfloat162_rn(x0, x1);
    return *(uint32_t*)&v;
}
__device__ __forceinline__ uint32_t pack2lo(float x0, float h0, float x1, float h1) {
    __nv_bfloat162 v = __floats2bfloat162_rn(x0 - h0, x1 - h1);
    return *(uint32_t*)&v;
}
__device__ __forceinline__ float bfu(uint32_t u) {
    return __bfloat162float(__ushort_as_bfloat16((unsigned short)(u & 0xffff)));
}

// C[R..R+15][0..127] (+)= A[R..R+15][:] * B[:][:]^T with A,B split hi/lo bf16.
// A tile at aHi/aLo, B tile ([n][k] row-major) at bHi/bLo; all pitch PB bytes.
__device__ __forceinline__ void gemm3(uint32_t aHi, uint32_t aLo,
                                      uint32_t bHi, uint32_t bLo,
                                      float (&c)[16][4], int R, int lid)
{
    const int lm = lid >> 3, lr = lid & 7;
    const uint32_t aoff = (uint32_t)(R + lr + ((lm & 1) << 3)) * PB + ((lm >> 1) << 4);
    const uint32_t boff = (uint32_t)(lr + ((lm >> 1) << 3)) * PB + ((lm & 1) << 4);
#pragma unroll 2
    for (int k = 0; k < 8; k++) {
        uint32_t ah[4], al[4];
        ldsm4(ah, aHi + aoff + k * 32);
        ldsm4(al, aLo + aoff + k * 32);
#pragma unroll
        for (int jp = 0; jp < 8; jp++) {
            uint32_t bh[4], bl[4];
            uint32_t bo = boff + (uint32_t)(jp * 16) * PB + k * 32;
            ldsm4(bh, bHi + bo);
            ldsm4(bl, bLo + bo);
            mma16816(c[2 * jp],     ah, bh);
            mma16816(c[2 * jp + 1], ah, bh + 2);
            mma16816(c[2 * jp],     ah, bl);
            mma16816(c[2 * jp + 1], ah, bl + 2);
            mma16816(c[2 * jp],     al, bh);
            mma16816(c[2 * jp + 1], al, bh + 2);
        }
    }
}

// ---------------- setup kernels ----------------
__global__ void setup_small(const float* __restrict__ te, const float* __restrict__ W_in,
                            const float* __restrict__ b_in, const float* __restrict__ om_i,
                            const float* __restrict__ om_c, const int* __restrict__ adj,
                            const int* __restrict__ et, float* __restrict__ out_tail) {
    int t = threadIdx.x;
    if (t < 64) {
        float w = 0.0f;
        if (adj[t] != 0) { int e = et[t]; w = (e == 1) ? om_i[0] : ((e == 2) ? om_c[0] : 1.0f); }
        g_ew[t] = w;
        out_tail[t] = w;
    }
    for (int idx = t; idx < 8 * 128; idx += blockDim.x) {
        int n = idx >> 7, o = idx & 127;
        const float* tr = te + n * 64;
        const float* wr = W_in + o * 64;
        float s = b_in[o];
#pragma unroll 8
        for (int d = 0; d < 64; d++) s += tr[d] * wr[d];
        g_htask[idx] = s;
    }
}

__global__ void build_images(const float* __restrict__ Wh, const float* __restrict__ OW) {
    int i = blockIdx.x * blockDim.x + threadIdx.x;
    int stride = gridDim.x * blockDim.x;
    for (int idx = i; idx < 8 * 16384; idx += stride) {
        int t = idx >> 14, rem = idx & 16383, row = rem >> 7, col = rem & 127;
        float w = Wh[idx];                      // W_heads[t][g=row][f=col]
        __nv_bfloat16 h = __float2bfloat16(w);
        g_Whi[idx] = h;
        g_Wlo[idx] = __float2bfloat16(w - __bfloat162float(h));
        int l = t >> 2, hh = t & 3;             // out_W[l][c=row][hh*128+g=col]
        float w2 = OW[l * 65536 + row * 512 + hh * 128 + col];
        __nv_bfloat16 h2 = __float2bfloat16(w2);
        g_OWhi[idx] = h2;
        g_OWlo[idx] = __float2bfloat16(w2 - __bfloat162float(h2));
    }
}

// ---------------- main kernel ----------------
__global__ __launch_bounds__(256, 1)
void gat_tc(const float* __restrict__ se, const float* __restrict__ a_heads,
            const float* __restrict__ out_b, const float* __restrict__ ln_s,
            const float* __restrict__ ln_b, const int* __restrict__ adj,
            float* __restrict__ out)
{
    extern __shared__ __align__(1024) unsigned char sm[];
    float* smf   = (float*)(sm + SM_SMALL);
    float* ei_s  = smf;              // [128]
    float* ej_s  = smf + 128;        // [128]
    float* att_s = smf + 256;        // [128][9]
    float* sa    = smf + 1408;       // [256]
    float* lnb   = smf + 1664;       // [384]
    float* ewf   = smf + 2048;       // [64]
    int*   adji  = (int*)(smf + 2112);

    const uint32_t smb = smem_u32(sm);
    const int tid = threadIdx.x;
    const int lid = tid & 31;
    const int wid = tid >> 5;
    const int R   = wid << 4;                 // this warp's 16 output rows
    const long b0 = (long)blockIdx.x * 16;

    if (tid < 64) { ewf[tid] = g_ew[tid]; adji[tid] = adj[tid]; }

    // ---- build h tiles: row r = bb*8+nn; hi/lo bf16, pitch PB ----
    {
        int r = tid & 127, qt = tid >> 7;      // half of features
        int f0 = qt * 64;
        const float* ser = se + (b0 + (r >> 3)) * 128;
        const float* htr = g_htask + (r & 7) * 128;
        for (int j = 0; j < 64; j += 2) {
            int f = f0 + j;
            float x0 = ser[f] + htr[f];
            float x1 = ser[f + 1] + htr[f + 1];
            uint32_t hiw = pack2(x0, x1);
            *(uint32_t*)(sm + SM_HHI + r * PB + f * 2) = hiw;
            *(uint32_t*)(sm + SM_HLO + r * PB + f * 2) =
                pack2lo(x0, bfu(hiw), x1, bfu(hiw >> 16));
        }
    }

    for (int l = 0; l < 2; l++) {
        float gacc[16][4];
#pragma unroll
        for (int i = 0; i < 16; i++)
#pragma unroll
            for (int j = 0; j < 4; j++) gacc[i][j] = 0.0f;

        for (int hh = 0; hh < 4; hh++) {
            const int t = l * 4 + hh;
            __syncthreads();   // prior GEMM2 reads of pHi / h-tile writes complete

            // ---- stage W hi/lo into pHi/pLo (pitch PB) ----
            {
                const uint4* wh = (const uint4*)(g_Whi + (t << 14));
                const uint4* wl = (const uint4*)(g_Wlo + (t << 14));
                uint4* dh = (uint4*)(sm + SM_PHI);
                uint4* dl = (uint4*)(sm + SM_PLO);
                for (int i = tid; i < 2048; i += 256) {
                    int r = i >> 4, c = i & 15;
                    dh[r * 17 + c] = wh[i];
                    dl[r * 17 + c] = wl[i];
                }
            }
            sa[tid] = a_heads[t * 256 + tid];
            if (hh == 0 && tid < 128) {
                lnb[tid]       = out_b[l * 128 + tid];
                lnb[128 + tid] = ln_s[l * 128 + tid];
                lnb[256 + tid] = ln_b[l * 128 + tid];
            }
            __syncthreads();

            // ---- GEMM1: Whh = h @ W^T ----
            float cacc[16][4];
#pragma unroll
            for (int i = 0; i < 16; i++)
#pragma unroll
                for (int j = 0; j < 4; j++) cacc[i][j] = 0.0f;
            gemm3(smb + SM_HHI, smb + SM_HLO, smb + SM_PHI, smb + SM_PLO, cacc, R, lid);

            // spill Whh fp32 -> scratch (S region)
            {
                float* scr = (float*)(sm + SM_S);
                int group = lid >> 2, tg = lid & 3;
#pragma unroll
                for (int jp = 0; jp < 16; jp++) {
                    int col = jp * 8 + tg * 2;
                    *(float2*)&scr[(R + group) * SCRP + col]     = make_float2(cacc[jp][0], cacc[jp][1]);
                    *(float2*)&scr[(R + group + 8) * SCRP + col] = make_float2(cacc[jp][2], cacc[jp][3]);
                }
            }
            __syncthreads();

            // ---- ei / ej ----
            {
                int r = tid & 127;
                const float* srow = (const float*)(sm + SM_S) + r * SCRP;
                const float* av = sa + ((tid >> 7) << 7);    // a_src or a_dst
                float s = 0.f;
#pragma unroll 4
                for (int g = 0; g < 128; g++) s += srow[g] * av[g];
                if (tid < 128) ei_s[r] = s; else ej_s[r] = s;
            }
            __syncthreads();

            // ---- softmax (row tid<128), masked-logit=0 faithful path ----
            if (tid < 128) {
                int bb = tid >> 3, nn = tid & 7;
                float ein = ei_s[tid];
                float lg[8], mx = -1e30f;
#pragma unroll
                for (int m = 0; m < 8; m++) {
                    float v = 0.f;
                    if (adji[nn * 8 + m]) {
                        float x = ein + ej_s[bb * 8 + m];
                        v = (x > 0.f ? x : 0.2f * x) * ewf[nn * 8 + m];
                    }
                    lg[m] = v;
                    mx = fmaxf(mx, v);
                }
                float s = 0.f;
#pragma unroll
                for (int m = 0; m < 8; m++) { lg[m] = __expf(lg[m] - mx); s += lg[m]; }
                float inv = 1.f / s;
#pragma unroll
                for (int m = 0; m < 8; m++) att_s[tid * 9 + m] = lg[m] * inv;
            }
            __syncthreads();

            // ---- hp = elu(att @ Whh) -> pHi/pLo (overwrite W) ----
            {
                int r = tid & 127, half = (tid >> 7) * 64;
                int bb = r >> 3;
                float aw[8];
#pragma unroll
                for (int m = 0; m < 8; m++) aw[m] = att_s[r * 9 + m];
                float acc[64];
#pragma unroll
                for (int j = 0; j < 64; j++) acc[j] = 0.f;
#pragma unroll
                for (int m = 0; m < 8; m++) {
                    float a = aw[m];
                    const float4* row4 =
                        (const float4*)((const float*)(sm + SM_S) + (bb * 8 + m) * SCRP + half);
#pragma unroll
                    for (int q = 0; q < 16; q++) {
                        float4 v = row4[q];
                        acc[q * 4 + 0] += a * v.x; acc[q * 4 + 1] += a * v.y;
                        acc[q * 4 + 2] += a * v.z; acc[q * 4 + 3] += a * v.w;
                    }
                }
#pragma unroll
                for (int j = 0; j < 64; j += 2) {
                    float x0 = acc[j], x1 = acc[j + 1];
                    x0 = x0 > 0.f ? x0 : (__expf(x0) - 1.f);
                    x1 = x1 > 0.f ? x1 : (__expf(x1) - 1.f);
                    uint32_t hiw = pack2(x0, x1);
                    int g = half + j;
                    *(uint32_t*)(sm + SM_PHI + r * PB + g * 2) = hiw;
                    *(uint32_t*)(sm + SM_PLO + r * PB + g * 2) =
                        pack2lo(x0, bfu(hiw), x1, bfu(hiw >> 16));
                }
            }
            __syncthreads();

            // ---- stage outW hi/lo into S region (overwrite scratch) ----
            {
                const uint4* oh = (const uint4*)(g_OWhi + (t << 14));
                const uint4* ol = (const uint4*)(g_OWlo + (t << 14));
                uint4* dh = (uint4*)(sm + SM_S);
                uint4* dl = (uint4*)(sm + SM_SLO);
                for (int i = tid; i < 2048; i += 256) {
                    int r = i >> 4, c = i & 15;
                    dh[r * 17 + c] = oh[i];
                    dl[r * 17 + c] = ol[i];
                }
            }
            __syncthreads();

            // ---- GEMM2: gacc += hp @ outW^T (accumulated across heads) ----
            gemm3(smb + SM_PHI, smb + SM_PLO, smb + SM_S, smb + SM_SLO, gacc, R, lid);
        } // heads

        __syncthreads();

        // ---- residual + bias + LayerNorm, fully in-register per warp ----
        {
            int group = lid >> 2, tg = lid & 3;
            int r0 = R + group, r1 = r0 + 8;
            float s0 = 0.f, q0 = 0.f, s1 = 0.f, q1 = 0.f;
#pragma unroll
            for (int jp = 0; jp < 16; jp++) {
                int col = jp * 8 + tg * 2;
                uint32_t h0h = *(uint32_t*)(sm + SM_HHI + r0 * PB + col * 2);
                uint32_t h0l = *(uint32_t*)(sm + SM_HLO + r0 * PB + col * 2);
                uint32_t h1h = *(uint32_t*)(sm + SM_HHI + r1 * PB + col * 2);
                uint32_t h1l = *(uint32_t*)(sm + SM_HLO + r1 * PB + col * 2);
                float x00 = gacc[jp][0] + bfu(h0h) + bfu(h0l) + lnb[col];
                float x01 = gacc[jp][1] + bfu(h0h >> 16) + bfu(h0l >> 16) + lnb[col + 1];
                float x10 = gacc[jp][2] + bfu(h1h) + bfu(h1l) + lnb[col];
                float x11 = gacc[jp][3] + bfu(h1h >> 16) + bfu(h1l >> 16) + lnb[col + 1];
                s0 += x00 + x01; q0 += x00 * x00 + x01 * x01;
                s1 += x10 + x11; q1 += x10 * x10 + x11 * x11;
            }
#pragma unroll
            for (int o = 1; o < 4; o <<= 1) {
                s0 += __shfl_xor_sync(0xffffffffu, s0, o);
                q0 += __shfl_xor_sync(0xffffffffu, q0, o);
                s1 += __shfl_xor_sync(0xffffffffu, s1, o);
                q1 += __shfl_xor_sync(0xffffffffu, q1, o);
            }
            float mu0 = s0 * 0.0078125f, mu1 = s1 * 0.0078125f;
            float rstd0 = rsqrtf(q0 * 0.0078125f - mu0 * mu0 + 1e-5f);
            float rstd1 = rsqrtf(q1 * 0.0078125f - mu1 * mu1 + 1e-5f);

#pragma unroll
            for (int jp = 0; jp < 16; jp++) {
                int col = jp * 8 + tg * 2;
                uint32_t h0h = *(uint32_t*)(sm + SM_HHI + r0 * PB + col * 2);
                uint32_t h0l = *(uint32_t*)(sm + SM_HLO + r0 * PB + col * 2);
                uint32_t h1h = *(uint32_t*)(sm + SM_HHI + r1 * PB + col * 2);
                uint32_t h1l = *(uint32_t*)(sm + SM_HLO + r1 * PB + col * 2);
                float x00 = gacc[jp][0] + bfu(h0h) + bfu(h0l) + lnb[col];
                float x01 = gacc[jp][1] + bfu(h0h >> 16) + bfu(h0l >> 16) + lnb[col + 1];
                float x10 = gacc[jp][2] + bfu(h1h) + bfu(h1l) + lnb[col];
                float x11 = gacc[jp][3] + bfu(h1h >> 16) + bfu(h1l >> 16) + lnb[col + 1];
                float y00 = (x00 - mu0) * rstd0 * lnb[128 + col]     + lnb[256 + col];
                float y01 = (x01 - mu0) * rstd0 * lnb[128 + col + 1] + lnb[256 + col + 1];
                float y10 = (x10 - mu1) * rstd1 * lnb[128 + col]     + lnb[256 + col];
                float y11 = (x11 - mu1) * rstd1 * lnb[128 + col + 1] + lnb[256 + col + 1];
                if (l == 0) {
                    uint32_t w0 = pack2(y00, y01);
                    uint32_t w1 = pack2(y10, y11);
                    *(uint32_t*)(sm + SM_HHI + r0 * PB + col * 2) = w0;
                    *(uint32_t*)(sm + SM_HLO + r0 * PB + col * 2) =
                        pack2lo(y00, bfu(w0), y01, bfu(w0 >> 16));
                    *(uint32_t*)(sm + SM_HHI + r1 * PB + col * 2) = w1;
                    *(uint32_t*)(sm + SM_HLO + r1 * PB + col * 2) =
                        pack2lo(y10, bfu(w1), y11, bfu(w1 >> 16));
                } else {
                    *(float2*)(out + (b0 * 8 + r0) * 128 + col) = make_float2(y00, y01);
                    *(float2*)(out + (b0 * 8 + r1) * 128 + col) = make_float2(y10, y11);
                }
            }
        }
    } // layers
}

// ---------------------------------------------------------------------------
extern "C" void kernel_launch(void* const* d_in, const int* in_sizes, int n_in,
                              void* d_out, int out_size)
{
    const float* se      = (const float*)d_in[0];
    const float* te      = (const float*)d_in[1];
    const float* W_in    = (const float*)d_in[2];
    const float* b_in    = (const float*)d_in[3];
    const float* W_heads = (const float*)d_in[4];
    const float* a_heads = (const float*)d_in[5];
    const float* out_W   = (const float*)d_in[6];
    const float* out_b   = (const float*)d_in[7];
    const float* ln_s    = (const float*)d_in[8];
    const float* ln_b    = (const float*)d_in[9];
    const float* om_i    = (const float*)d_in[10];
    const float* om_c    = (const float*)d_in[11];
    const int*   adj     = (const int*)d_in[12];
    const int*   et      = (const int*)d_in[13];
    float* out = (float*)d_out;

    int B = in_sizes[0] / 128;
    size_t tail = (size_t)B * 8 * 128;

    setup_small<<<1, 512>>>(te, W_in, b_in, om_i, om_c, adj, et, out + tail);
    build_images<<<256, 256>>>(W_heads, out_W);

    cudaFuncSetAttribute(gat_tc, cudaFuncAttributeMaxDynamicSharedMemorySize, SMEM_BYTES);
    gat_tc<<<B / 16, 256, SMEM_BYTES>>>(se, a_heads, out_b, ln_s, ln_b, adj, out);
}

// round 5
// speedup vs baseline: 3.2036x; 1.1573x over previous
#include <cuda_runtime.h>
#include <cuda_bf16.h>
#include <cstdint>
#include <math.h>

// ===========================================================================
// TaskGraphGAT — round 5: HMMA bf16 3-product, warp-local attention,
// register A-fragments for GEMM2, cp.async weight prefetch, single setup.
// 1 CTA = 16 batch elems = 128 rows; warp w owns rows 16w..16w+15 = 2 batches.
// ===========================================================================

#define PB   272        // bf16 tile pitch in BYTES (136 bf16), LDSM conflict-free

// ---------------- SMEM map (bytes) ----------------
#define SM_HHI   0          // h hi (128 x 136 bf16 = 34816 B)
#define SM_HLO   34816
#define SM_PHI   69632      // W hi/lo (GEMM1 B)
#define SM_PLO   104448
#define SM_S     139264     // outW hi/lo (GEMM2 B)
#define SM_SLO   174080
#define SM_SMALL 208896     // sa[2][256] | lnb[2][384] | ewf[64] | adji[64]
#define SMEM_BYTES 214528

// ---------------- device globals (written by prep) ----------------
__device__ float g_htask[8 * 128];
__device__ __align__(16) __nv_bfloat16 g_Whi[8 * 16384];
__device__ __align__(16) __nv_bfloat16 g_Wlo[8 * 16384];
__device__ __align__(16) __nv_bfloat16 g_OWhi[8 * 16384];
__device__ __align__(16) __nv_bfloat16 g_OWlo[8 * 16384];

// ---------------- helpers ----------------
__device__ __forceinline__ uint32_t smem_u32(const void* p) {
    uint32_t a;
    asm("{ .reg .u64 t; cvta.to.shared.u64 t, %1; cvt.u32.u64 %0, t; }" : "=r"(a) : "l"(p));
    return a;
}
__device__ __forceinline__ void ldsm4(uint32_t* r, uint32_t a) {
    asm volatile("ldmatrix.sync.aligned.m8n8.x4.shared.b16 {%0,%1,%2,%3}, [%4];"
                 : "=r"(r[0]), "=r"(r[1]), "=r"(r[2]), "=r"(r[3]) : "r"(a));
}
__device__ __forceinline__ void mma16816(float* c, const uint32_t* a, const uint32_t* b) {
    asm volatile(
        "mma.sync.aligned.m16n8k16.row.col.f32.bf16.bf16.f32 "
        "{%0,%1,%2,%3}, {%4,%5,%6,%7}, {%8,%9}, {%0,%1,%2,%3};"
        : "+f"(c[0]), "+f"(c[1]), "+f"(c[2]), "+f"(c[3])
        : "r"(a[0]), "r"(a[1]), "r"(a[2]), "r"(a[3]), "r"(b[0]), "r"(b[1]));
}
__device__ __forceinline__ void cpa16(uint32_t dst, const void* src) {
    asm volatile("cp.async.cg.shared.global [%0], [%1], 16;" :: "r"(dst), "l"(src));
}
#define CP_COMMIT() asm volatile("cp.async.commit_group;" ::: "memory")
#define CP_WAIT0()  asm volatile("cp.async.wait_group 0;" ::: "memory")

__device__ __forceinline__ uint32_t pack2(float x0, float x1) {
    __nv_bfloat162 v = __floats2bfloat162_rn(x0, x1);
    return *(uint32_t*)&v;
}
__device__ __forceinline__ uint32_t pack2lo(float x0, float h0, float x1, float h1) {
    __nv_bfloat162 v = __floats2bfloat162_rn(x0 - h0, x1 - h1);
    return *(uint32_t*)&v;
}
__device__ __forceinline__ float bfu(uint32_t u) {
    return __bfloat162float(__ushort_as_bfloat16((unsigned short)(u & 0xffff)));
}

// stage a hi/lo bf16 128x128 tile pair into pitched SMEM via cp.async
__device__ __forceinline__ void stage_pair(uint32_t dhi, uint32_t dlo,
                                           const uint4* shi, const uint4* slo, int tid) {
#pragma unroll
    for (int i = tid; i < 2048; i += 256) {
        uint32_t d = ((uint32_t)(i >> 4) * PB) + ((i & 15) << 4);
        cpa16(dhi + d, shi + i);
        cpa16(dlo + d, slo + i);
    }
}

// GEMM1: cacc[q][0..3] += A(hi/lo)[rows R..R+15] @ B(hi/lo)^T, cols q*8+tg*2(+1)
__device__ __forceinline__ void gemm1(uint32_t aHi, uint32_t aLo,
                                      uint32_t bHi, uint32_t bLo,
                                      float (&c)[16][4], int R, int lid) {
    const int lm = lid >> 3, lr = lid & 7;
    const uint32_t aoff = (uint32_t)(R + lr + ((lm & 1) << 3)) * PB + ((lm >> 1) << 4);
    const uint32_t boff = (uint32_t)(lr + ((lm >> 1) << 3)) * PB + ((lm & 1) << 4);
#pragma unroll 2
    for (int k = 0; k < 8; k++) {
        uint32_t ah[4], al[4];
        ldsm4(ah, aHi + aoff + k * 32);
        ldsm4(al, aLo + aoff + k * 32);
#pragma unroll
        for (int jp = 0; jp < 8; jp++) {
            uint32_t bh[4], bl[4];
            uint32_t bo = boff + (uint32_t)(jp * 16) * PB + k * 32;
            ldsm4(bh, bHi + bo);
            ldsm4(bl, bLo + bo);
            mma16816(c[2 * jp],     ah, bh);
            mma16816(c[2 * jp + 1], ah, bh + 2);
            mma16816(c[2 * jp],     ah, bl);
            mma16816(c[2 * jp + 1], ah, bl + 2);
            mma16816(c[2 * jp],     al, bh);
            mma16816(c[2 * jp + 1], al, bh + 2);
        }
    }
}

// ---------------- single setup kernel ----------------
__global__ void prep(const float* __restrict__ te, const float* __restrict__ W_in,
                     const float* __restrict__ b_in, const float* __restrict__ Wh,
                     const float* __restrict__ OW, const float* __restrict__ om_i,
                     const float* __restrict__ om_c, const int* __restrict__ adj,
                     const int* __restrict__ et, float* __restrict__ out_tail) {
    int gtid = blockIdx.x * 256 + threadIdx.x;
#pragma unroll
    for (int u = 0; u < 2; u++) {
        int idx = gtid + u * 65536;
        int t = idx >> 14, rem = idx & 16383, row = rem >> 7, col = rem & 127;
        float w = Wh[idx];                       // W_heads[t][g=row][f=col]
        __nv_bfloat16 h = __float2bfloat16(w);
        g_Whi[idx] = h;
        g_Wlo[idx] = __float2bfloat16(w - __bfloat162float(h));
        int l = t >> 2, hh = t & 3;              // out_W[l][c=row][hh*128+g=col]
        float w2 = OW[l * 65536 + row * 512 + hh * 128 + col];
        __nv_bfloat16 h2 = __float2bfloat16(w2);
        g_OWhi[idx] = h2;
        g_OWlo[idx] = __float2bfloat16(w2 - __bfloat162float(h2));
    }
    if (blockIdx.x == 0) {
        int t = threadIdx.x;
        if (t < 64) {
            float w = 0.f;
            if (adj[t]) { int e = et[t]; w = (e == 1) ? om_i[0] : ((e == 2) ? om_c[0] : 1.f); }
            out_tail[t] = w;
        }
        for (int idx = t; idx < 1024; idx += 256) {
            int n = idx >> 7, o = idx & 127;
            const float* tr = te + n * 64;
            const float* wr = W_in + o * 64;
            float s = b_in[o];
#pragma unroll 8
            for (int d = 0; d < 64; d++) s += tr[d] * wr[d];
            g_htask[idx] = s;
        }
    }
}

// ---------------- main kernel ----------------
__global__ __launch_bounds__(256, 1)
void gat_tc(const float* __restrict__ se, const float* __restrict__ a_heads,
            const float* __restrict__ out_b, const float* __restrict__ ln_s,
            const float* __restrict__ ln_b, const int* __restrict__ adj,
            const int* __restrict__ et, const float* __restrict__ om_i,
            const float* __restrict__ om_c, float* __restrict__ out)
{
    extern __shared__ __align__(1024) unsigned char sm[];
    float* smf  = (float*)(sm + SM_SMALL);
    float* sa   = smf;                // [2][256]
    float* lnb  = smf + 512;          // [2][384]: out_b | ln_scale | ln_bias
    float* ewf  = smf + 1280;         // [64]
    int*   adji = (int*)(smf + 1344); // [64]

    const uint32_t smb = smem_u32(sm);
    const int tid = threadIdx.x;
    const int lid = tid & 31;
    const int wid = tid >> 5;
    const int R     = wid << 4;
    const int group = lid >> 2;
    const int tg    = lid & 3;
    const long b0 = (long)blockIdx.x * 16;

    // ---- prefetch head-0 weights ASAP ----
    stage_pair(smb + SM_PHI, smb + SM_PLO, (const uint4*)g_Whi,  (const uint4*)g_Wlo,  tid);
    stage_pair(smb + SM_S,   smb + SM_SLO, (const uint4*)g_OWhi, (const uint4*)g_OWlo, tid);
    CP_COMMIT();

    // ---- small constants ----
    if (tid < 64) {
        int e = et[tid];
        ewf[tid] = adj[tid] ? ((e == 1) ? om_i[0] : ((e == 2) ? om_c[0] : 1.f)) : 0.f;
        adji[tid] = adj[tid];
    }
    sa[tid] = a_heads[tid];
    if (tid < 128) {
#pragma unroll
        for (int l = 0; l < 2; l++) {
            lnb[l * 384 + tid]       = out_b[l * 128 + tid];
            lnb[l * 384 + 128 + tid] = ln_s[l * 128 + tid];
            lnb[l * 384 + 256 + tid] = ln_b[l * 128 + tid];
        }
    }

    // ---- build h tiles (hi/lo bf16): row r = bb*8+nn ----
    {
        int r = tid & 127, f0 = (tid >> 7) * 64;
        const float* ser = se + (b0 + (r >> 3)) * 128;
        const float* htr = g_htask + (r & 7) * 128;
#pragma unroll 8
        for (int j = 0; j < 64; j += 2) {
            int f = f0 + j;
            float x0 = ser[f] + htr[f];
            float x1 = ser[f + 1] + htr[f + 1];
            uint32_t hiw = pack2(x0, x1);
            *(uint32_t*)(sm + SM_HHI + r * PB + f * 2) = hiw;
            *(uint32_t*)(sm + SM_HLO + r * PB + f * 2) =
                pack2lo(x0, bfu(hiw), x1, bfu(hiw >> 16));
        }
    }
    CP_WAIT0();
    __syncthreads();

    for (int l = 0; l < 2; l++) {
        float gacc[16][4];
#pragma unroll
        for (int i = 0; i < 16; i++)
#pragma unroll
            for (int j = 0; j < 4; j++) gacc[i][j] = 0.0f;

        for (int hh = 0; hh < 4; hh++) {
            const int t = l * 4 + hh;
            const int buf = t & 1;
            if (t > 0) { CP_WAIT0(); __syncthreads(); }   // W[t], outW[t], sa landed

            // ---- GEMM1: cacc = h @ W^T ----
            float cacc[16][4];
#pragma unroll
            for (int i = 0; i < 16; i++)
#pragma unroll
                for (int j = 0; j < 4; j++) cacc[i][j] = 0.0f;
            gemm1(smb + SM_HHI, smb + SM_HLO, smb + SM_PHI, smb + SM_PLO, cacc, R, lid);

            // ---- ei/ej partials from fragments + quad reduce ----
            float ei0 = 0.f, ej0 = 0.f, ei1 = 0.f, ej1 = 0.f;
            {
                const float* sav = sa + buf * 256;
#pragma unroll
                for (int q = 0; q < 16; q++) {
                    float s0 = sav[q * 8 + tg * 2], s1 = sav[q * 8 + tg * 2 + 1];
                    float d0 = sav[128 + q * 8 + tg * 2], d1 = sav[128 + q * 8 + tg * 2 + 1];
                    ei0 += cacc[q][0] * s0 + cacc[q][1] * s1;
                    ej0 += cacc[q][0] * d0 + cacc[q][1] * d1;
                    ei1 += cacc[q][2] * s0 + cacc[q][3] * s1;
                    ej1 += cacc[q][2] * d0 + cacc[q][3] * d1;
                }
#pragma unroll
                for (int o = 1; o < 4; o <<= 1) {
                    ei0 += __shfl_xor_sync(0xffffffffu, ei0, o);
                    ej0 += __shfl_xor_sync(0xffffffffu, ej0, o);
                    ei1 += __shfl_xor_sync(0xffffffffu, ei1, o);
                    ej1 += __shfl_xor_sync(0xffffffffu, ej1, o);
                }
            }

            __syncthreads();   // #1: all warps done reading W + sa[buf]
            if (t < 7) {       // prefetch next W (lands during softmax/hp/GEMM2)
                stage_pair(smb + SM_PHI, smb + SM_PLO,
                           (const uint4*)(g_Whi + ((t + 1) << 14)),
                           (const uint4*)(g_Wlo + ((t + 1) << 14)), tid);
                CP_COMMIT();
                sa[(buf ^ 1) * 256 + tid] = a_heads[(t + 1) * 256 + tid];
            }

            // ---- warp-local softmax for rows r0=R+group (batch0), r1=r0+8 (batch1) ----
            float att0[8], att1[8];
            {
                float mx0 = -1e30f, mx1 = -1e30f;
#pragma unroll
                for (int m = 0; m < 8; m++) {
                    float ejm0 = __shfl_sync(0xffffffffu, ej0, m * 4 + tg);
                    float ejm1 = __shfl_sync(0xffffffffu, ej1, m * 4 + tg);
                    float w = ewf[group * 8 + m];
                    int   ad = adji[group * 8 + m];
                    float v0 = 0.f, v1 = 0.f;
                    if (ad) {
                        float x0 = ei0 + ejm0; v0 = (x0 > 0.f ? x0 : 0.2f * x0) * w;
                        float x1 = ei1 + ejm1; v1 = (x1 > 0.f ? x1 : 0.2f * x1) * w;
                    }
                    att0[m] = v0; att1[m] = v1;
                    mx0 = fmaxf(mx0, v0); mx1 = fmaxf(mx1, v1);
                }
                float s0 = 0.f, s1 = 0.f;
#pragma unroll
                for (int m = 0; m < 8; m++) {
                    att0[m] = __expf(att0[m] - mx0); s0 += att0[m];
                    att1[m] = __expf(att1[m] - mx1); s1 += att1[m];
                }
                float i0 = 1.f / s0, i1 = 1.f / s1;
#pragma unroll
                for (int m = 0; m < 8; m++) { att0[m] *= i0; att1[m] *= i1; }
            }

            // ---- hp = elu(att @ Whh) via warp shuffles -> GEMM2 A-fragments ----
            uint32_t afHi[8][4], afLo[8][4];
#pragma unroll
            for (int q = 0; q < 16; q++) {
                float h0a = 0.f, h0b = 0.f, h1a = 0.f, h1b = 0.f;
#pragma unroll
                for (int m = 0; m < 8; m++) {
                    int src = m * 4 + tg;
                    float w0 = __shfl_sync(0xffffffffu, cacc[q][0], src);
                    float w1 = __shfl_sync(0xffffffffu, cacc[q][1], src);
                    float w2 = __shfl_sync(0xffffffffu, cacc[q][2], src);
                    float w3 = __shfl_sync(0xffffffffu, cacc[q][3], src);
                    h0a += att0[m] * w0; h0b += att0[m] * w1;
                    h1a += att1[m] * w2; h1b += att1[m] * w3;
                }
                h0a = h0a > 0.f ? h0a : (__expf(h0a) - 1.f);
                h0b = h0b > 0.f ? h0b : (__expf(h0b) - 1.f);
                h1a = h1a > 0.f ? h1a : (__expf(h1a) - 1.f);
                h1b = h1b > 0.f ? h1b : (__expf(h1b) - 1.f);
                uint32_t p0 = pack2(h0a, h0b), p1 = pack2(h1a, h1b);
                int kk = q >> 1, pos = (q & 1) << 1;
                afHi[kk][pos]     = p0;
                afHi[kk][pos + 1] = p1;
                afLo[kk][pos]     = pack2lo(h0a, bfu(p0), h0b, bfu(p0 >> 16));
                afLo[kk][pos + 1] = pack2lo(h1a, bfu(p1), h1b, bfu(p1 >> 16));
            }

            // ---- GEMM2: gacc += hp @ outW^T (A from registers, B from SMEM) ----
            {
                const int lm = lid >> 3, lr = lid & 7;
                const uint32_t boff = (uint32_t)(lr + ((lm >> 1) << 3)) * PB + ((lm & 1) << 4);
                const uint32_t bS = smb + SM_S, bSL = smb + SM_SLO;
#pragma unroll
                for (int kk = 0; kk < 8; kk++) {
#pragma unroll
                    for (int jp = 0; jp < 8; jp++) {
                        uint32_t bh[4], bl[4];
                        uint32_t bo = boff + (uint32_t)(jp * 16) * PB + kk * 32;
                        ldsm4(bh, bS + bo);
                        ldsm4(bl, bSL + bo);
                        mma16816(gacc[2 * jp],     afHi[kk], bh);
                        mma16816(gacc[2 * jp + 1], afHi[kk], bh + 2);
                        mma16816(gacc[2 * jp],     afHi[kk], bl);
                        mma16816(gacc[2 * jp + 1], afHi[kk], bl + 2);
                        mma16816(gacc[2 * jp],     afLo[kk], bh);
                        mma16816(gacc[2 * jp + 1], afLo[kk], bh + 2);
                    }
                }
            }

            __syncthreads();   // #2: all warps done reading outW (S)
            if (t < 7) {       // prefetch next outW
                stage_pair(smb + SM_S, smb + SM_SLO,
                           (const uint4*)(g_OWhi + ((t + 1) << 14)),
                           (const uint4*)(g_OWlo + ((t + 1) << 14)), tid);
                CP_COMMIT();
            }
        } // heads

        // ---- residual + bias + LayerNorm (warp-local rows) ----
        {
            const float* lb = lnb + l * 384;
            int r0 = R + group, r1 = r0 + 8;
            float s0 = 0.f, q0 = 0.f, s1 = 0.f, q1 = 0.f;
            float x0v[16][2], x1v[16][2];
#pragma unroll
            for (int jp = 0; jp < 16; jp++) {
                int col = jp * 8 + tg * 2;
                uint32_t h0h = *(uint32_t*)(sm + SM_HHI + r0 * PB + col * 2);
                uint32_t h0l = *(uint32_t*)(sm + SM_HLO + r0 * PB + col * 2);
                uint32_t h1h = *(uint32_t*)(sm + SM_HHI + r1 * PB + col * 2);
                uint32_t h1l = *(uint32_t*)(sm + SM_HLO + r1 * PB + col * 2);
                float x00 = gacc[jp][0] + bfu(h0h) + bfu(h0l) + lb[col];
                float x01 = gacc[jp][1] + bfu(h0h >> 16) + bfu(h0l >> 16) + lb[col + 1];
                float x10 = gacc[jp][2] + bfu(h1h) + bfu(h1l) + lb[col];
                float x11 = gacc[jp][3] + bfu(h1h >> 16) + bfu(h1l >> 16) + lb[col + 1];
                x0v[jp][0] = x00; x0v[jp][1] = x01;
                x1v[jp][0] = x10; x1v[jp][1] = x11;
                s0 += x00 + x01; q0 += x00 * x00 + x01 * x01;
                s1 += x10 + x11; q1 += x10 * x10 + x11 * x11;
            }
#pragma unroll
            for (int o = 1; o < 4; o <<= 1) {
                s0 += __shfl_xor_sync(0xffffffffu, s0, o);
                q0 += __shfl_xor_sync(0xffffffffu, q0, o);
                s1 += __shfl_xor_sync(0xffffffffu, s1, o);
                q1 += __shfl_xor_sync(0xffffffffu, q1, o);
            }
            float mu0 = s0 * 0.0078125f, mu1 = s1 * 0.0078125f;
            float rstd0 = rsqrtf(q0 * 0.0078125f - mu0 * mu0 + 1e-5f);
            float rstd1 = rsqrtf(q1 * 0.0078125f - mu1 * mu1 + 1e-5f);
#pragma unroll
            for (int jp = 0; jp < 16; jp++) {
                int col = jp * 8 + tg * 2;
                float y00 = (x0v[jp][0] - mu0) * rstd0 * lb[128 + col]     + lb[256 + col];
                float y01 = (x0v[jp][1] - mu0) * rstd0 * lb[128 + col + 1] + lb[256 + col + 1];
                float y10 = (x1v[jp][0] - mu1) * rstd1 * lb[128 + col]     + lb[256 + col];
                float y11 = (x1v[jp][1] - mu1) * rstd1 * lb[128 + col + 1] + lb[256 + col + 1];
                if (l == 0) {
                    uint32_t w0 = pack2(y00, y01), w1 = pack2(y10, y11);
                    *(uint32_t*)(sm + SM_HHI + r0 * PB + col * 2) = w0;
                    *(uint32_t*)(sm + SM_HLO + r0 * PB + col * 2) =
                        pack2lo(y00, bfu(w0), y01, bfu(w0 >> 16));
                    *(uint32_t*)(sm + SM_HHI + r1 * PB + col * 2) = w1;
                    *(uint32_t*)(sm + SM_HLO + r1 * PB + col * 2) =
                        pack2lo(y10, bfu(w1), y11, bfu(w1 >> 16));
                } else {
                    *(float2*)(out + (b0 * 8 + r0) * 128 + col) = make_float2(y00, y01);
                    *(float2*)(out + (b0 * 8 + r1) * 128 + col) = make_float2(y10, y11);
                }
            }
            __syncwarp();   // h-tile writes visible to next-layer GEMM1 (warp-local)
        }
    } // layers
}

// ---------------------------------------------------------------------------
extern "C" void kernel_launch(void* const* d_in, const int* in_sizes, int n_in,
                              void* d_out, int out_size)
{
    const float* se      = (const float*)d_in[0];
    const float* te      = (const float*)d_in[1];
    const float* W_in    = (const float*)d_in[2];
    const float* b_in    = (const float*)d_in[3];
    const float* W_heads = (const float*)d_in[4];
    const float* a_heads = (const float*)d_in[5];
    const float* out_W   = (const float*)d_in[6];
    const float* out_b   = (const float*)d_in[7];
    const float* ln_s    = (const float*)d_in[8];
    const float* ln_b    = (const float*)d_in[9];
    const float* om_i    = (const float*)d_in[10];
    const float* om_c    = (const float*)d_in[11];
    const int*   adj     = (const int*)d_in[12];
    const int*   et      = (const int*)d_in[13];
    float* out = (float*)d_out;

    int B = in_sizes[0] / 128;
    size_t tail = (size_t)B * 8 * 128;

    prep<<<256, 256>>>(te, W_in, b_in, W_heads, out_W, om_i, om_c, adj, et, out + tail);

    cudaFuncSetAttribute(gat_tc, cudaFuncAttributeMaxDynamicSharedMemorySize, SMEM_BYTES);
    gat_tc<<<B / 16, 256, SMEM_BYTES>>>(se, a_heads, out_b, ln_s, ln_b,
                                        adj, et, om_i, om_c, out);
}